// round 5
// baseline (speedup 1.0000x reference)
#include <cuda_runtime.h>
#include <math.h>

#define NSNPS  500000
#define NGENES 20000
#define NNODES 600000
#define NEDGES 320000
#define NB     16
#define NF     8

// rsqrt(1 + 1e-5)
#define BN_RS 0.9999950000374997f

// -------- scratch (static device allocations; no runtime alloc) --------
__device__ float d_snpT[(size_t)NSNPS * NB];     // 32 MB  [snp][b]
__device__ float d_fT[(size_t)NSNPS * NF];       // 16 MB  [snp][f]
__device__ float d_hA[(size_t)NGENES * NB * NF]; // 10.24 MB [g][b][f]
__device__ float d_hB[(size_t)NGENES * NB * NF];
__device__ int   d_seg[NGENES + 1];
__device__ int   d_deg[NGENES];
__device__ int   d_cur[NGENES];   // running write cursor (init = offsets, by k_scan)
__device__ int   d_off[NGENES + 1];
__device__ int   d_csr[NEDGES];
__device__ float d_gh[NB * NF];

__device__ __forceinline__ float gelu_f(float x) { return x * normcdff(x); }

// -------- init: zero deg/gh + per-gene node-segment starts (gon sorted) --------
__global__ void k_init(const int* __restrict__ gon) {
    int i = blockIdx.x * blockDim.x + threadIdx.x;
    if (i < NGENES) d_deg[i] = 0;
    if (i < NB * NF) d_gh[i] = 0.f;
    if (i <= NGENES) {
        int lo = 0, hi = NNODES;
        while (lo < hi) {
            int mid = (lo + hi) >> 1;
            if (gon[mid] < i) lo = mid + 1; else hi = mid;
        }
        d_seg[i] = lo;
    }
}

// -------- CSR build: histogram, scan(+cursor init), scatter --------
__global__ void k_hist(const int* __restrict__ dst) {
    int e = blockIdx.x * blockDim.x + threadIdx.x;
    if (e < NEDGES) atomicAdd(&d_deg[dst[e]], 1);
}

__global__ void k_scan() {
    __shared__ int sh[1024];
    const int PER = (NGENES + 1023) / 1024;  // 20
    int tid = threadIdx.x;
    int base = tid * PER;
    int s = 0;
    for (int i = 0; i < PER; i++) {
        int idx = base + i;
        if (idx < NGENES) s += d_deg[idx];
    }
    sh[tid] = s;
    __syncthreads();
    for (int off = 1; off < 1024; off <<= 1) {
        int add = 0;
        if (tid >= off) add = sh[tid - off];
        __syncthreads();
        sh[tid] += add;
        __syncthreads();
    }
    int run = (tid == 0) ? 0 : sh[tid - 1];
    for (int i = 0; i < PER; i++) {
        int idx = base + i;
        if (idx < NGENES) {
            d_off[idx] = run;
            d_cur[idx] = run;
            run += d_deg[idx];
        }
    }
    if (tid == 1023) d_off[NGENES] = run;
}

__global__ void k_scatter(const int* __restrict__ src, const int* __restrict__ dst) {
    int e = blockIdx.x * blockDim.x + threadIdx.x;
    if (e >= NEDGES) return;
    int p = atomicAdd(&d_cur[dst[e]], 1);
    d_csr[p] = src[e];
}

// -------- transpose snp -> snpT, filters -> fT, copy filters out (4 snps/thread) --------
__global__ void __launch_bounds__(256) k_pre(const float* __restrict__ snp,
                                             const float* __restrict__ filters,
                                             float* __restrict__ outF) {
    int t4 = (blockIdx.x * blockDim.x + threadIdx.x) * 4;
    if (t4 >= NSNPS) return;
    float4 v[NB];
#pragma unroll
    for (int b = 0; b < NB; b++)
        v[b] = *(const float4*)&snp[(size_t)b * NSNPS + t4];
#pragma unroll
    for (int i = 0; i < 4; i++) {
        float* row = &d_snpT[(size_t)(t4 + i) * NB];
        float4* rp = (float4*)row;
        const float* vv = (const float*)v;  // v[b] component i at vv[b*4+i]
        rp[0] = make_float4(vv[0 * 4 + i],  vv[1 * 4 + i],  vv[2 * 4 + i],  vv[3 * 4 + i]);
        rp[1] = make_float4(vv[4 * 4 + i],  vv[5 * 4 + i],  vv[6 * 4 + i],  vv[7 * 4 + i]);
        rp[2] = make_float4(vv[8 * 4 + i],  vv[9 * 4 + i],  vv[10 * 4 + i], vv[11 * 4 + i]);
        rp[3] = make_float4(vv[12 * 4 + i], vv[13 * 4 + i], vv[14 * 4 + i], vv[15 * 4 + i]);
    }
    float4 w[NF];
#pragma unroll
    for (int f = 0; f < NF; f++) {
        w[f] = *(const float4*)&filters[(size_t)f * NSNPS + t4];
        *(float4*)&outF[(size_t)f * NSNPS + t4] = w[f];
    }
    const float* ww = (const float*)w;
#pragma unroll
    for (int i = 0; i < 4; i++) {
        float4* fp = (float4*)&d_fT[(size_t)(t4 + i) * NF];
        fp[0] = make_float4(ww[0 * 4 + i], ww[1 * 4 + i], ww[2 * 4 + i], ww[3 * 4 + i]);
        fp[1] = make_float4(ww[4 * 4 + i], ww[5 * 4 + i], ww[6 * 4 + i], ww[7 * 4 + i]);
    }
}

// -------- SNP -> gene readout (unroll-4, index prefetch) --------
__global__ void k_gene(const int* __restrict__ snp_ids) {
    int tid = threadIdx.x;
    int g = blockIdx.x * 16 + (tid >> 4);
    int b = tid & 15;
    if (g >= NGENES) return;
    float4 a0 = make_float4(0.f, 0.f, 0.f, 0.f);
    float4 a1 = a0;
    int n0 = d_seg[g], n1 = d_seg[g + 1];
    int n = n0;
    for (; n + 4 <= n1; n += 4) {
        int i0 = snp_ids[n], i1 = snp_ids[n + 1], i2 = snp_ids[n + 2], i3 = snp_ids[n + 3];
        float s0 = d_snpT[(size_t)i0 * NB + b];
        float s1 = d_snpT[(size_t)i1 * NB + b];
        float s2 = d_snpT[(size_t)i2 * NB + b];
        float s3 = d_snpT[(size_t)i3 * NB + b];
        const float4* p0 = (const float4*)&d_fT[(size_t)i0 * NF];
        const float4* p1 = (const float4*)&d_fT[(size_t)i1 * NF];
        const float4* p2 = (const float4*)&d_fT[(size_t)i2 * NF];
        const float4* p3 = (const float4*)&d_fT[(size_t)i3 * NF];
        float4 f00 = p0[0], f01 = p0[1];
        float4 f10 = p1[0], f11 = p1[1];
        float4 f20 = p2[0], f21 = p2[1];
        float4 f30 = p3[0], f31 = p3[1];
        a0.x += s0 * f00.x; a0.y += s0 * f00.y; a0.z += s0 * f00.z; a0.w += s0 * f00.w;
        a1.x += s0 * f01.x; a1.y += s0 * f01.y; a1.z += s0 * f01.z; a1.w += s0 * f01.w;
        a0.x += s1 * f10.x; a0.y += s1 * f10.y; a0.z += s1 * f10.z; a0.w += s1 * f10.w;
        a1.x += s1 * f11.x; a1.y += s1 * f11.y; a1.z += s1 * f11.z; a1.w += s1 * f11.w;
        a0.x += s2 * f20.x; a0.y += s2 * f20.y; a0.z += s2 * f20.z; a0.w += s2 * f20.w;
        a1.x += s2 * f21.x; a1.y += s2 * f21.y; a1.z += s2 * f21.z; a1.w += s2 * f21.w;
        a0.x += s3 * f30.x; a0.y += s3 * f30.y; a0.z += s3 * f30.z; a0.w += s3 * f30.w;
        a1.x += s3 * f31.x; a1.y += s3 * f31.y; a1.z += s3 * f31.z; a1.w += s3 * f31.w;
    }
    for (; n < n1; n++) {
        int id = snp_ids[n];
        float sv = d_snpT[(size_t)id * NB + b];
        const float4* fp = (const float4*)&d_fT[(size_t)id * NF];
        float4 f0 = fp[0], f1 = fp[1];
        a0.x += sv * f0.x; a0.y += sv * f0.y; a0.z += sv * f0.z; a0.w += sv * f0.w;
        a1.x += sv * f1.x; a1.y += sv * f1.y; a1.z += sv * f1.z; a1.w += sv * f1.w;
    }
    float4* hp = (float4*)&d_hA[((size_t)g * NB + b) * NF];
    hp[0] = a0; hp[1] = a1;
}

// -------- edge aggregation core (unroll-4, index prefetch) --------
__device__ __forceinline__ void edge_agg(const float* __restrict__ hin,
                                         int g, int b, float ep, float acc[8]) {
    const float4* hp = (const float4*)&hin[((size_t)g * NB + b) * NF];
    float4 a0 = hp[0], a1 = hp[1];
    a0.x *= ep; a0.y *= ep; a0.z *= ep; a0.w *= ep;
    a1.x *= ep; a1.y *= ep; a1.z *= ep; a1.w *= ep;
    int e0 = d_off[g], e1 = d_off[g + 1];
    int e = e0;
    for (; e + 4 <= e1; e += 4) {
        int s0 = d_csr[e], s1 = d_csr[e + 1], s2 = d_csr[e + 2], s3 = d_csr[e + 3];
        const float4* p0 = (const float4*)&hin[((size_t)s0 * NB + b) * NF];
        const float4* p1 = (const float4*)&hin[((size_t)s1 * NB + b) * NF];
        const float4* p2 = (const float4*)&hin[((size_t)s2 * NB + b) * NF];
        const float4* p3 = (const float4*)&hin[((size_t)s3 * NB + b) * NF];
        float4 x00 = p0[0], x01 = p0[1];
        float4 x10 = p1[0], x11 = p1[1];
        float4 x20 = p2[0], x21 = p2[1];
        float4 x30 = p3[0], x31 = p3[1];
        a0.x += x00.x + x10.x + x20.x + x30.x;
        a0.y += x00.y + x10.y + x20.y + x30.y;
        a0.z += x00.z + x10.z + x20.z + x30.z;
        a0.w += x00.w + x10.w + x20.w + x30.w;
        a1.x += x01.x + x11.x + x21.x + x31.x;
        a1.y += x01.y + x11.y + x21.y + x31.y;
        a1.z += x01.z + x11.z + x21.z + x31.z;
        a1.w += x01.w + x11.w + x21.w + x31.w;
    }
    for (; e < e1; e++) {
        int s = d_csr[e];
        const float4* sp = (const float4*)&hin[((size_t)s * NB + b) * NF];
        float4 x0 = sp[0], x1 = sp[1];
        a0.x += x0.x; a0.y += x0.y; a0.z += x0.z; a0.w += x0.w;
        a1.x += x1.x; a1.y += x1.y; a1.z += x1.z; a1.w += x1.w;
    }
    acc[0] = a0.x; acc[1] = a0.y; acc[2] = a0.z; acc[3] = a0.w;
    acc[4] = a1.x; acc[5] = a1.y; acc[6] = a1.z; acc[7] = a1.w;
}

// -------- GIN MLP(8->16->8)+BN+GELU from smem-held weights --------
__device__ __forceinline__ void gin_mlp(const float acc[8], float o[8],
                                        const float* sW1, const float* sB1,
                                        const float* sG1, const float* sT1,
                                        const float* sW2, const float* sB2,
                                        const float* sG2, const float* sT2) {
    float h2[16];
#pragma unroll
    for (int j = 0; j < 16; j++) {
        float t = sB1[j];
#pragma unroll
        for (int f = 0; f < 8; f++) t += acc[f] * sW1[f * 16 + j];
        h2[j] = gelu_f(t * sG1[j] + sT1[j]);
    }
#pragma unroll
    for (int f = 0; f < 8; f++) {
        float t = sB2[f];
#pragma unroll
        for (int j = 0; j < 16; j++) t += h2[j] * sW2[j * 8 + f];
        o[f] = gelu_f(t * sG2[f] + sT2[f]);
    }
}

// -------- layer 0: hA -> hB --------
__global__ void k_layer0(const float* __restrict__ eps,
                         const float* __restrict__ W1, const float* __restrict__ b1,
                         const float* __restrict__ g1, const float* __restrict__ bt1,
                         const float* __restrict__ W2, const float* __restrict__ b2,
                         const float* __restrict__ g2, const float* __restrict__ bt2) {
    __shared__ float sW1[128], sW2[128], sB1[16], sG1[16], sT1[16], sB2[8], sG2[8], sT2[8];
    int tid = threadIdx.x;
    if (tid < 128) { sW1[tid] = W1[tid]; sW2[tid] = W2[tid]; }
    if (tid < 16) { sB1[tid] = b1[tid]; sG1[tid] = g1[tid] * BN_RS; sT1[tid] = bt1[tid]; }
    if (tid < 8)  { sB2[tid] = b2[tid]; sG2[tid] = g2[tid] * BN_RS; sT2[tid] = bt2[tid]; }
    __syncthreads();

    int g = blockIdx.x * 16 + (tid >> 4);
    int b = tid & 15;
    if (g >= NGENES) return;
    float acc[8], o[8];
    edge_agg(d_hA, g, b, 1.f + eps[0], acc);
    gin_mlp(acc, o, sW1, sB1, sG1, sT1, sW2, sB2, sG2, sT2);
    float4* op = (float4*)&d_hB[((size_t)g * NB + b) * NF];
    op[0] = make_float4(o[0], o[1], o[2], o[3]);
    op[1] = make_float4(o[4], o[5], o[6], o[7]);
}

// -------- layer 1 fused with attentive readout: hB -> (w_out, d_gh), no h store --------
__global__ void k_layer1_attn(const float* __restrict__ eps,
                              const float* __restrict__ W1, const float* __restrict__ b1,
                              const float* __restrict__ g1, const float* __restrict__ bt1,
                              const float* __restrict__ W2, const float* __restrict__ b2,
                              const float* __restrict__ g2, const float* __restrict__ bt2,
                              const float* __restrict__ Wk, const float* __restrict__ bk,
                              const float* __restrict__ Wq,
                              const float* __restrict__ Wv, const float* __restrict__ bv,
                              float* __restrict__ w_out) {
    __shared__ float sW1[128], sW2[128], sB1[16], sG1[16], sT1[16], sB2[8], sG2[8], sT2[8];
    __shared__ float sWk[64], sWv[64], sWq[8], sBk[8], sBv[8];
    __shared__ float red[8][16][8];  // [warp][b][f]
    int tid = threadIdx.x;
    if (tid < 128) { sW1[tid] = W1[128 + tid]; sW2[tid] = W2[128 + tid]; }
    if (tid < 16) { sB1[tid] = b1[16 + tid]; sG1[tid] = g1[16 + tid] * BN_RS; sT1[tid] = bt1[16 + tid]; }
    if (tid < 8)  { sB2[tid] = b2[8 + tid]; sG2[tid] = g2[8 + tid] * BN_RS; sT2[tid] = bt2[8 + tid]; }
    if (tid >= 128 && tid < 192) { sWk[tid - 128] = Wk[tid - 128]; sWv[tid - 128] = Wv[tid - 128]; }
    if (tid >= 192 && tid < 200) {
        int j = tid - 192;
        sWq[j] = Wq[j]; sBk[j] = bk[j]; sBv[j] = bv[j];
    }
    __syncthreads();

    int g = blockIdx.x * 16 + (tid >> 4);
    int b = tid & 15;
    float vw[8];
    {
        float acc[8], o[8];
        edge_agg(d_hB, g, b, 1.f + eps[1], acc);
        gin_mlp(acc, o, sW1, sB1, sG1, sT1, sW2, sB2, sG2, sT2);
        // attention: q = (key(o)) . Wq ; w = sigmoid(q) ; vw = value(o) * w
        float q = 0.f;
#pragma unroll
        for (int j = 0; j < 8; j++) {
            float key = sBk[j];
#pragma unroll
            for (int f = 0; f < 8; f++) key += o[f] * sWk[f * 8 + j];
            q += key * sWq[j];
        }
        float wv = 1.f / (1.f + expf(-q));
        w_out[(size_t)b * NGENES + g] = wv;
#pragma unroll
        for (int j = 0; j < 8; j++) {
            float v = sBv[j];
#pragma unroll
            for (int f = 0; f < 8; f++) v += o[f] * sWv[f * 8 + j];
            vw[j] = v * wv;
        }
    }
    // combine the two genes in each warp (lanes 0-15 get lane+16's values)
#pragma unroll
    for (int j = 0; j < 8; j++) vw[j] += __shfl_down_sync(0xffffffffu, vw[j], 16);
    int wid = tid >> 5, lane = tid & 31;
    if (lane < 16) {
#pragma unroll
        for (int j = 0; j < 8; j++) red[wid][lane][j] = vw[j];
    }
    __syncthreads();
    // 128 threads: one per (b, f); sum 8 warps then one global atomic each
    if (tid < 128) {
        int bb = tid >> 3, f = tid & 7;
        float s = 0.f;
#pragma unroll
        for (int w = 0; w < 8; w++) s += red[w][bb][f];
        atomicAdd(&d_gh[bb * NF + f], s);
    }
}

// -------- final MLP head: 8 -> 64 -> 16 -> 1 --------
__global__ void k_head(const float* __restrict__ Wp1, const float* __restrict__ bp1,
                       const float* __restrict__ gp1, const float* __restrict__ btp1,
                       const float* __restrict__ Wp2, const float* __restrict__ bp2,
                       const float* __restrict__ gp2, const float* __restrict__ btp2,
                       const float* __restrict__ Wp3, const float* __restrict__ bp3,
                       float* __restrict__ preds) {
    int b = threadIdx.x;
    if (b >= NB) return;
    float x[8];
#pragma unroll
    for (int f = 0; f < 8; f++) x[f] = d_gh[b * 8 + f];
    float z1[64];
    for (int j = 0; j < 64; j++) {
        float t = bp1[j];
#pragma unroll
        for (int f = 0; f < 8; f++) t += x[f] * Wp1[f * 64 + j];
        z1[j] = gelu_f(t * BN_RS * gp1[j] + btp1[j]);
    }
    float z2[16];
    for (int k = 0; k < 16; k++) {
        float t = bp2[k];
        for (int j = 0; j < 64; j++) t += z1[j] * Wp2[j * 16 + k];
        z2[k] = gelu_f(t * BN_RS * gp2[k] + btp2[k]);
    }
    float p = bp3[0];
#pragma unroll
    for (int k = 0; k < 16; k++) p += z2[k] * Wp3[k];
    preds[b] = p;
}

extern "C" void kernel_launch(void* const* d_in, const int* in_sizes, int n_in,
                              void* d_out, int out_size) {
    const float* snp     = (const float*)d_in[0];
    const int*   snp_ids = (const int*)d_in[1];
    const int*   gon     = (const int*)d_in[2];
    const int*   esrc    = (const int*)d_in[3];
    const int*   edst    = (const int*)d_in[4];
    const float* filters = (const float*)d_in[5];
    const float* eps     = (const float*)d_in[6];
    const float* W1  = (const float*)d_in[7];
    const float* b1  = (const float*)d_in[8];
    const float* g1  = (const float*)d_in[9];
    const float* bt1 = (const float*)d_in[10];
    const float* W2  = (const float*)d_in[11];
    const float* b2  = (const float*)d_in[12];
    const float* g2  = (const float*)d_in[13];
    const float* bt2 = (const float*)d_in[14];
    const float* Wk  = (const float*)d_in[15];
    const float* bk  = (const float*)d_in[16];
    const float* Wq  = (const float*)d_in[17];
    const float* Wv  = (const float*)d_in[18];
    const float* bv  = (const float*)d_in[19];
    const float* Wp1 = (const float*)d_in[20];
    const float* bp1 = (const float*)d_in[21];
    const float* gp1 = (const float*)d_in[22];
    const float* btp1= (const float*)d_in[23];
    const float* Wp2 = (const float*)d_in[24];
    const float* bp2 = (const float*)d_in[25];
    const float* gp2 = (const float*)d_in[26];
    const float* btp2= (const float*)d_in[27];
    const float* Wp3 = (const float*)d_in[28];
    const float* bp3 = (const float*)d_in[29];

    float* out   = (float*)d_out;
    float* preds = out;                               // [16]
    float* outF  = out + NB;                          // [8*500000]
    float* w_out = out + NB + (size_t)NF * NSNPS;     // [16*20000]

    k_init<<<(NGENES + 1 + 255) / 256, 256>>>(gon);
    k_hist<<<(NEDGES + 255) / 256, 256>>>(edst);
    k_scan<<<1, 1024>>>();
    k_scatter<<<(NEDGES + 255) / 256, 256>>>(esrc, edst);
    k_pre<<<(NSNPS / 4 + 255) / 256, 256>>>(snp, filters, outF);
    k_gene<<<NGENES / 16, 256>>>(snp_ids);
    k_layer0<<<NGENES / 16, 256>>>(eps, W1, b1, g1, bt1, W2, b2, g2, bt2);
    k_layer1_attn<<<NGENES / 16, 256>>>(eps, W1, b1, g1, bt1, W2, b2, g2, bt2,
                                        Wk, bk, Wq, Wv, bv, w_out);
    k_head<<<1, 32>>>(Wp1, bp1, gp1, btp1, Wp2, bp2, gp2, btp2, Wp3, bp3, preds);
}

// round 7
// speedup vs baseline: 1.4446x; 1.4446x over previous
#include <cuda_runtime.h>
#include <math.h>

#define NSNPS  500000
#define NGENES 20000
#define NNODES 600000
#define NEDGES 320000
#define NB     16
#define NF     8

#define SCAT_BLOCKS ((NEDGES + 255) / 256)   // 1250
#define PRE_BLOCKS  ((NSNPS + 255) / 256)    // 1954

// rsqrt(1 + 1e-5)
#define BN_RS 0.9999950000374997f

// -------- scratch (static device allocations; zero-initialized at load) --------
__device__ float d_snpT[(size_t)NSNPS * NB];     // 32 MB  [snp][b]
__device__ float d_fT[(size_t)NSNPS * NF];       // 16 MB  [snp][f]
__device__ float d_hA[(size_t)NGENES * NB * NF]; // 10.24 MB [g][b][f]
__device__ float d_hB[(size_t)NGENES * NB * NF];
__device__ int   d_seg[NGENES + 1];
__device__ int   d_deg[NGENES];   // INVARIANT: zero on kernel_launch entry (k_scan re-zeros)
__device__ int   d_cur[NGENES];
__device__ int   d_off[NGENES + 1];
__device__ int   d_csr[NEDGES];
__device__ float d_gh[NB * NF];   // INVARIANT: zero on entry (k_head re-zeros)

__device__ __forceinline__ float gelu_f(float x) { return x * normcdff(x); }

// -------- launch 1: edge-degree histogram + per-gene node-segment starts --------
__global__ void k_hist_seg(const int* __restrict__ dst, const int* __restrict__ gon) {
    int i = blockIdx.x * blockDim.x + threadIdx.x;
    if (i <= NGENES) {
        int lo = 0, hi = NNODES;
        while (lo < hi) {
            int mid = (lo + hi) >> 1;
            if (gon[mid] < i) lo = mid + 1; else hi = mid;
        }
        d_seg[i] = lo;
    }
    if (i < NEDGES) atomicAdd(&d_deg[dst[i]], 1);
}

// -------- launch 2: exclusive scan of deg -> off/cur; re-zero deg --------
__global__ void k_scan() {
    __shared__ int sh[1024];
    const int PER = (NGENES + 1023) / 1024;  // 20
    int tid = threadIdx.x;
    int base = tid * PER;
    int s = 0;
    for (int i = 0; i < PER; i++) {
        int idx = base + i;
        if (idx < NGENES) s += d_deg[idx];
    }
    sh[tid] = s;
    __syncthreads();
    for (int off = 1; off < 1024; off <<= 1) {
        int add = 0;
        if (tid >= off) add = sh[tid - off];
        __syncthreads();
        sh[tid] += add;
        __syncthreads();
    }
    int run = (tid == 0) ? 0 : sh[tid - 1];
    for (int i = 0; i < PER; i++) {
        int idx = base + i;
        if (idx < NGENES) {
            d_off[idx] = run;
            d_cur[idx] = run;
            run += d_deg[idx];
            d_deg[idx] = 0;   // restore invariant for next graph replay
        }
    }
    if (tid == 1023) d_off[NGENES] = run;
}

// -------- launch 3: CSR scatter (blocks 0..1249) + transpose/pre (blocks 1250..) --------
__global__ void __launch_bounds__(256) k_scatter_pre(
        const int* __restrict__ src, const int* __restrict__ dst,
        const float* __restrict__ snp, const float* __restrict__ filters,
        float* __restrict__ outF) {
    __shared__ float smem_s[256][NB + 1];   // +1 pad: conflict-free
    __shared__ float smem_f[256][NF + 1];
    int tid = threadIdx.x;

    if (blockIdx.x < SCAT_BLOCKS) {
        int e = blockIdx.x * 256 + tid;
        if (e < NEDGES) {
            int p = atomicAdd(&d_cur[dst[e]], 1);
            d_csr[p] = src[e];
        }
        return;
    }

    int t0 = (blockIdx.x - SCAT_BLOCKS) * 256;
    int t = t0 + tid;
    bool ok = (t < NSNPS);
#pragma unroll
    for (int b = 0; b < NB; b++)
        smem_s[tid][b] = ok ? snp[(size_t)b * NSNPS + t] : 0.f;
#pragma unroll
    for (int f = 0; f < NF; f++) {
        float w = ok ? filters[(size_t)f * NSNPS + t] : 0.f;
        smem_f[tid][f] = w;
        if (ok) outF[(size_t)f * NSNPS + t] = w;
    }
    __syncthreads();
    if (ok) {
        float4* dp = (float4*)&d_snpT[(size_t)t * NB];
        dp[0] = make_float4(smem_s[tid][0],  smem_s[tid][1],  smem_s[tid][2],  smem_s[tid][3]);
        dp[1] = make_float4(smem_s[tid][4],  smem_s[tid][5],  smem_s[tid][6],  smem_s[tid][7]);
        dp[2] = make_float4(smem_s[tid][8],  smem_s[tid][9],  smem_s[tid][10], smem_s[tid][11]);
        dp[3] = make_float4(smem_s[tid][12], smem_s[tid][13], smem_s[tid][14], smem_s[tid][15]);
        float4* fp = (float4*)&d_fT[(size_t)t * NF];
        fp[0] = make_float4(smem_f[tid][0], smem_f[tid][1], smem_f[tid][2], smem_f[tid][3]);
        fp[1] = make_float4(smem_f[tid][4], smem_f[tid][5], smem_f[tid][6], smem_f[tid][7]);
    }
}

// -------- launch 4 (PROFILED): SNP -> gene readout (unroll-4, index prefetch) --------
__global__ void k_gene(const int* __restrict__ snp_ids) {
    int tid = threadIdx.x;
    int g = blockIdx.x * 16 + (tid >> 4);
    int b = tid & 15;
    float4 a0 = make_float4(0.f, 0.f, 0.f, 0.f);
    float4 a1 = a0;
    int n0 = d_seg[g], n1 = d_seg[g + 1];
    int n = n0;
    for (; n + 4 <= n1; n += 4) {
        int i0 = snp_ids[n], i1 = snp_ids[n + 1], i2 = snp_ids[n + 2], i3 = snp_ids[n + 3];
        float s0 = d_snpT[(size_t)i0 * NB + b];
        float s1 = d_snpT[(size_t)i1 * NB + b];
        float s2 = d_snpT[(size_t)i2 * NB + b];
        float s3 = d_snpT[(size_t)i3 * NB + b];
        const float4* p0 = (const float4*)&d_fT[(size_t)i0 * NF];
        const float4* p1 = (const float4*)&d_fT[(size_t)i1 * NF];
        const float4* p2 = (const float4*)&d_fT[(size_t)i2 * NF];
        const float4* p3 = (const float4*)&d_fT[(size_t)i3 * NF];
        float4 f00 = p0[0], f01 = p0[1];
        float4 f10 = p1[0], f11 = p1[1];
        float4 f20 = p2[0], f21 = p2[1];
        float4 f30 = p3[0], f31 = p3[1];
        a0.x += s0 * f00.x; a0.y += s0 * f00.y; a0.z += s0 * f00.z; a0.w += s0 * f00.w;
        a1.x += s0 * f01.x; a1.y += s0 * f01.y; a1.z += s0 * f01.z; a1.w += s0 * f01.w;
        a0.x += s1 * f10.x; a0.y += s1 * f10.y; a0.z += s1 * f10.z; a0.w += s1 * f10.w;
        a1.x += s1 * f11.x; a1.y += s1 * f11.y; a1.z += s1 * f11.z; a1.w += s1 * f11.w;
        a0.x += s2 * f20.x; a0.y += s2 * f20.y; a0.z += s2 * f20.z; a0.w += s2 * f20.w;
        a1.x += s2 * f21.x; a1.y += s2 * f21.y; a1.z += s2 * f21.z; a1.w += s2 * f21.w;
        a0.x += s3 * f30.x; a0.y += s3 * f30.y; a0.z += s3 * f30.z; a0.w += s3 * f30.w;
        a1.x += s3 * f31.x; a1.y += s3 * f31.y; a1.z += s3 * f31.z; a1.w += s3 * f31.w;
    }
    for (; n < n1; n++) {
        int id = snp_ids[n];
        float sv = d_snpT[(size_t)id * NB + b];
        const float4* fp = (const float4*)&d_fT[(size_t)id * NF];
        float4 f0 = fp[0], f1 = fp[1];
        a0.x += sv * f0.x; a0.y += sv * f0.y; a0.z += sv * f0.z; a0.w += sv * f0.w;
        a1.x += sv * f1.x; a1.y += sv * f1.y; a1.z += sv * f1.z; a1.w += sv * f1.w;
    }
    float4* hp = (float4*)&d_hA[((size_t)g * NB + b) * NF];
    hp[0] = a0; hp[1] = a1;
}

// -------- edge aggregation core (unroll-2: bounded registers) --------
__device__ __forceinline__ void edge_agg(const float* __restrict__ hin,
                                         int g, int b, float ep, float acc[8]) {
    const float4* hp = (const float4*)&hin[((size_t)g * NB + b) * NF];
    float4 a0 = hp[0], a1 = hp[1];
    a0.x *= ep; a0.y *= ep; a0.z *= ep; a0.w *= ep;
    a1.x *= ep; a1.y *= ep; a1.z *= ep; a1.w *= ep;
    int e0 = d_off[g], e1 = d_off[g + 1];
    int e = e0;
    for (; e + 2 <= e1; e += 2) {
        int s0 = d_csr[e], s1 = d_csr[e + 1];
        const float4* p0 = (const float4*)&hin[((size_t)s0 * NB + b) * NF];
        const float4* p1 = (const float4*)&hin[((size_t)s1 * NB + b) * NF];
        float4 x00 = p0[0], x01 = p0[1];
        float4 x10 = p1[0], x11 = p1[1];
        a0.x += x00.x + x10.x; a0.y += x00.y + x10.y;
        a0.z += x00.z + x10.z; a0.w += x00.w + x10.w;
        a1.x += x01.x + x11.x; a1.y += x01.y + x11.y;
        a1.z += x01.z + x11.z; a1.w += x01.w + x11.w;
    }
    if (e < e1) {
        int s = d_csr[e];
        const float4* sp = (const float4*)&hin[((size_t)s * NB + b) * NF];
        float4 x0 = sp[0], x1 = sp[1];
        a0.x += x0.x; a0.y += x0.y; a0.z += x0.z; a0.w += x0.w;
        a1.x += x1.x; a1.y += x1.y; a1.z += x1.z; a1.w += x1.w;
    }
    acc[0] = a0.x; acc[1] = a0.y; acc[2] = a0.z; acc[3] = a0.w;
    acc[4] = a1.x; acc[5] = a1.y; acc[6] = a1.z; acc[7] = a1.w;
}

// -------- GIN MLP(8->16->8)+BN+GELU from smem-held weights --------
__device__ __forceinline__ void gin_mlp(const float acc[8], float o[8],
                                        const float* sW1, const float* sB1,
                                        const float* sG1, const float* sT1,
                                        const float* sW2, const float* sB2,
                                        const float* sG2, const float* sT2) {
    float h2[16];
#pragma unroll
    for (int j = 0; j < 16; j++) {
        float t = sB1[j];
#pragma unroll
        for (int f = 0; f < 8; f++) t += acc[f] * sW1[f * 16 + j];
        h2[j] = gelu_f(t * sG1[j] + sT1[j]);
    }
#pragma unroll
    for (int f = 0; f < 8; f++) {
        float t = sB2[f];
#pragma unroll
        for (int j = 0; j < 16; j++) t += h2[j] * sW2[j * 8 + f];
        o[f] = gelu_f(t * sG2[f] + sT2[f]);
    }
}

// -------- launch 5: GIN layer 0: hA -> hB --------
__global__ void k_layer0(const float* __restrict__ eps,
                         const float* __restrict__ W1, const float* __restrict__ b1,
                         const float* __restrict__ g1, const float* __restrict__ bt1,
                         const float* __restrict__ W2, const float* __restrict__ b2,
                         const float* __restrict__ g2, const float* __restrict__ bt2) {
    __shared__ float sW1[128], sW2[128], sB1[16], sG1[16], sT1[16], sB2[8], sG2[8], sT2[8];
    int tid = threadIdx.x;
    if (tid < 128) { sW1[tid] = W1[tid]; sW2[tid] = W2[tid]; }
    if (tid < 16) { sB1[tid] = b1[tid]; sG1[tid] = g1[tid] * BN_RS; sT1[tid] = bt1[tid]; }
    if (tid < 8)  { sB2[tid] = b2[tid]; sG2[tid] = g2[tid] * BN_RS; sT2[tid] = bt2[tid]; }
    __syncthreads();

    int g = blockIdx.x * 16 + (tid >> 4);
    int b = tid & 15;
    float acc[8], o[8];
    edge_agg(d_hA, g, b, 1.f + eps[0], acc);
    gin_mlp(acc, o, sW1, sB1, sG1, sT1, sW2, sB2, sG2, sT2);
    float4* op = (float4*)&d_hB[((size_t)g * NB + b) * NF];
    op[0] = make_float4(o[0], o[1], o[2], o[3]);
    op[1] = make_float4(o[4], o[5], o[6], o[7]);
}

// -------- launch 6: GIN layer 1 fused with attentive readout --------
__global__ void k_layer1_attn(const float* __restrict__ eps,
                              const float* __restrict__ W1, const float* __restrict__ b1,
                              const float* __restrict__ g1, const float* __restrict__ bt1,
                              const float* __restrict__ W2, const float* __restrict__ b2,
                              const float* __restrict__ g2, const float* __restrict__ bt2,
                              const float* __restrict__ Wk, const float* __restrict__ bk,
                              const float* __restrict__ Wq,
                              const float* __restrict__ Wv, const float* __restrict__ bv,
                              float* __restrict__ w_out) {
    __shared__ float sW1[128], sW2[128], sB1[16], sG1[16], sT1[16], sB2[8], sG2[8], sT2[8];
    __shared__ float sWk[64], sWv[64], sWq[8], sBk[8], sBv[8];
    __shared__ float red[8][16][8];  // [warp][b][f]
    int tid = threadIdx.x;
    if (tid < 128) { sW1[tid] = W1[128 + tid]; sW2[tid] = W2[128 + tid]; }
    if (tid < 16) { sB1[tid] = b1[16 + tid]; sG1[tid] = g1[16 + tid] * BN_RS; sT1[tid] = bt1[16 + tid]; }
    if (tid < 8)  { sB2[tid] = b2[8 + tid]; sG2[tid] = g2[8 + tid] * BN_RS; sT2[tid] = bt2[8 + tid]; }
    if (tid >= 128 && tid < 192) { sWk[tid - 128] = Wk[tid - 128]; sWv[tid - 128] = Wv[tid - 128]; }
    if (tid >= 192 && tid < 200) {
        int j = tid - 192;
        sWq[j] = Wq[j]; sBk[j] = bk[j]; sBv[j] = bv[j];
    }
    __syncthreads();

    int g = blockIdx.x * 16 + (tid >> 4);
    int b = tid & 15;
    float vw[8];
    {
        float acc[8], o[8];
        edge_agg(d_hB, g, b, 1.f + eps[1], acc);
        gin_mlp(acc, o, sW1, sB1, sG1, sT1, sW2, sB2, sG2, sT2);
        float q = 0.f;
#pragma unroll
        for (int j = 0; j < 8; j++) {
            float key = sBk[j];
#pragma unroll
            for (int f = 0; f < 8; f++) key += o[f] * sWk[f * 8 + j];
            q += key * sWq[j];
        }
        float wv = 1.f / (1.f + expf(-q));
        w_out[(size_t)b * NGENES + g] = wv;
#pragma unroll
        for (int j = 0; j < 8; j++) {
            float v = sBv[j];
#pragma unroll
            for (int f = 0; f < 8; f++) v += o[f] * sWv[f * 8 + j];
            vw[j] = v * wv;
        }
    }
#pragma unroll
    for (int j = 0; j < 8; j++) vw[j] += __shfl_down_sync(0xffffffffu, vw[j], 16);
    int wid = tid >> 5, lane = tid & 31;
    if (lane < 16) {
#pragma unroll
        for (int j = 0; j < 8; j++) red[wid][lane][j] = vw[j];
    }
    __syncthreads();
    if (tid < 128) {
        int bb = tid >> 3, f = tid & 7;
        float s = 0.f;
#pragma unroll
        for (int w = 0; w < 8; w++) s += red[w][bb][f];
        atomicAdd(&d_gh[bb * NF + f], s);
    }
}

// -------- launch 7: final MLP head: 8 -> 64 -> 16 -> 1; re-zero d_gh --------
__global__ void k_head(const float* __restrict__ Wp1, const float* __restrict__ bp1,
                       const float* __restrict__ gp1, const float* __restrict__ btp1,
                       const float* __restrict__ Wp2, const float* __restrict__ bp2,
                       const float* __restrict__ gp2, const float* __restrict__ btp2,
                       const float* __restrict__ Wp3, const float* __restrict__ bp3,
                       float* __restrict__ preds) {
    int b = threadIdx.x;
    if (b < NB) {
        float x[8];
#pragma unroll
        for (int f = 0; f < 8; f++) x[f] = d_gh[b * 8 + f];
        float z1[64];
        for (int j = 0; j < 64; j++) {
            float t = bp1[j];
#pragma unroll
            for (int f = 0; f < 8; f++) t += x[f] * Wp1[f * 64 + j];
            z1[j] = gelu_f(t * BN_RS * gp1[j] + btp1[j]);
        }
        float z2[16];
        for (int k = 0; k < 16; k++) {
            float t = bp2[k];
            for (int j = 0; j < 64; j++) t += z1[j] * Wp2[j * 16 + k];
            z2[k] = gelu_f(t * BN_RS * gp2[k] + btp2[k]);
        }
        float p = bp3[0];
#pragma unroll
        for (int k = 0; k < 16; k++) p += z2[k] * Wp3[k];
        preds[b] = p;
    }
    __syncthreads();
    // restore invariant: d_gh must be zero for next graph replay
    for (int i = threadIdx.x; i < NB * NF; i += 32) d_gh[i] = 0.f;
}

extern "C" void kernel_launch(void* const* d_in, const int* in_sizes, int n_in,
                              void* d_out, int out_size) {
    const float* snp     = (const float*)d_in[0];
    const int*   snp_ids = (const int*)d_in[1];
    const int*   gon     = (const int*)d_in[2];
    const int*   esrc    = (const int*)d_in[3];
    const int*   edst    = (const int*)d_in[4];
    const float* filters = (const float*)d_in[5];
    const float* eps     = (const float*)d_in[6];
    const float* W1  = (const float*)d_in[7];
    const float* b1  = (const float*)d_in[8];
    const float* g1  = (const float*)d_in[9];
    const float* bt1 = (const float*)d_in[10];
    const float* W2  = (const float*)d_in[11];
    const float* b2  = (const float*)d_in[12];
    const float* g2  = (const float*)d_in[13];
    const float* bt2 = (const float*)d_in[14];
    const float* Wk  = (const float*)d_in[15];
    const float* bk  = (const float*)d_in[16];
    const float* Wq  = (const float*)d_in[17];
    const float* Wv  = (const float*)d_in[18];
    const float* bv  = (const float*)d_in[19];
    const float* Wp1 = (const float*)d_in[20];
    const float* bp1 = (const float*)d_in[21];
    const float* gp1 = (const float*)d_in[22];
    const float* btp1= (const float*)d_in[23];
    const float* Wp2 = (const float*)d_in[24];
    const float* bp2 = (const float*)d_in[25];
    const float* gp2 = (const float*)d_in[26];
    const float* btp2= (const float*)d_in[27];
    const float* Wp3 = (const float*)d_in[28];
    const float* bp3 = (const float*)d_in[29];

    float* out   = (float*)d_out;
    float* preds = out;                               // [16]
    float* outF  = out + NB;                          // [8*500000]
    float* w_out = out + NB + (size_t)NF * NSNPS;     // [16*20000]

    k_hist_seg<<<SCAT_BLOCKS, 256>>>(edst, gon);                               // 1
    k_scan<<<1, 1024>>>();                                                     // 2
    k_scatter_pre<<<SCAT_BLOCKS + PRE_BLOCKS, 256>>>(esrc, edst, snp, filters, outF); // 3
    k_gene<<<NGENES / 16, 256>>>(snp_ids);                                     // 4  <- profiled
    k_layer0<<<NGENES / 16, 256>>>(eps, W1, b1, g1, bt1, W2, b2, g2, bt2);     // 5
    k_layer1_attn<<<NGENES / 16, 256>>>(eps, W1, b1, g1, bt1, W2, b2, g2, bt2,
                                        Wk, bk, Wq, Wv, bv, w_out);            // 6
    k_head<<<1, 32>>>(Wp1, bp1, gp1, btp1, Wp2, bp2, gp2, btp2, Wp3, bp3, preds); // 7
}